// round 3
// baseline (speedup 1.0000x reference)
#include <cuda_runtime.h>
#include <cuda_bf16.h>
#include <math.h>

// Problem constants
#define BB 4
#define LL 512
#define DM 256
#define NL 6
#define DI 512
#define DS 16
#define DC 4
#define DTR 16
#define TT (BB * LL)        // 2048 tokens
#define XZW (2 * DI)        // 1024
#define RXW (DTR + 2 * DS)  // 48

// Scratch (device globals; no allocation allowed)
__device__ __align__(16) float g_xn[TT * DM];
__device__ __align__(16) float g_xz[TT * XZW];
__device__ __align__(16) float g_u[TT * DI];
__device__ __align__(16) float g_xdbc[TT * RXW];
__device__ __align__(16) float g_delta[TT * DI];
__device__ __align__(16) float g_y[TT * DI];
__device__ __align__(16) float g_yg[TT * DI];

// ---------------------------------------------------------------------------
// RMSNorm: one block per token, 256 threads (= DM)
// ---------------------------------------------------------------------------
__global__ void rmsnorm_kernel(const float* __restrict__ x,
                               const float* __restrict__ w,
                               float* __restrict__ out) {
    int t = blockIdx.x;
    int c = threadIdx.x;
    float v = x[t * DM + c];
    float sq = v * v;
#pragma unroll
    for (int o = 16; o > 0; o >>= 1) sq += __shfl_xor_sync(0xffffffffu, sq, o);
    __shared__ float sacc[8];
    if ((c & 31) == 0) sacc[c >> 5] = sq;
    __syncthreads();
    __shared__ float srs;
    if (c == 0) {
        float tot = 0.f;
#pragma unroll
        for (int i = 0; i < 8; i++) tot += sacc[i];
        srs = rsqrtf(tot / (float)DM + 1e-5f);
    }
    __syncthreads();
    out[t * DM + c] = v * srs * w[c];
}

// ---------------------------------------------------------------------------
// Generic TN GEMM: C[m,n] = sum_k A[m,k]*Bw[n,k] (+bias[n]) (+addsrc[m,n])
// A: [M,K] row-major, Bw: [N,K] row-major. K % 16 == 0, M % 64 == 0 assumed,
// N guarded. BM=BN=64, BK=16, 256 threads, 4x4 per thread.
// ---------------------------------------------------------------------------
__global__ void gemm_tn_kernel(const float* __restrict__ A,
                               const float* __restrict__ Bw,
                               const float* __restrict__ bias,
                               const float* __restrict__ addsrc,
                               float* __restrict__ C,
                               int M, int N, int K) {
    __shared__ float As[16][64 + 4];
    __shared__ float Bs[16][64 + 4];
    int tid = threadIdx.x;
    int bm = blockIdx.y * 64;
    int bn = blockIdx.x * 64;
    int tx = tid & 15;   // n sub-tile
    int ty = tid >> 4;   // m sub-tile
    int lrow = tid >> 2;        // 0..63
    int lcol = (tid & 3) * 4;   // 0,4,8,12

    float acc[4][4];
#pragma unroll
    for (int i = 0; i < 4; i++)
#pragma unroll
        for (int j = 0; j < 4; j++) acc[i][j] = 0.f;

    for (int k0 = 0; k0 < K; k0 += 16) {
        // load A tile (64 rows x 16 cols), transposed into As[k][m]
        {
            int gm = bm + lrow;
            float4 v = make_float4(0.f, 0.f, 0.f, 0.f);
            if (gm < M) v = *reinterpret_cast<const float4*>(&A[(size_t)gm * K + k0 + lcol]);
            As[lcol + 0][lrow] = v.x;
            As[lcol + 1][lrow] = v.y;
            As[lcol + 2][lrow] = v.z;
            As[lcol + 3][lrow] = v.w;
        }
        // load B tile (64 n-rows x 16 cols), transposed into Bs[k][n]
        {
            int gn = bn + lrow;
            float4 v = make_float4(0.f, 0.f, 0.f, 0.f);
            if (gn < N) v = *reinterpret_cast<const float4*>(&Bw[(size_t)gn * K + k0 + lcol]);
            Bs[lcol + 0][lrow] = v.x;
            Bs[lcol + 1][lrow] = v.y;
            Bs[lcol + 2][lrow] = v.z;
            Bs[lcol + 3][lrow] = v.w;
        }
        __syncthreads();
#pragma unroll
        for (int kk = 0; kk < 16; kk++) {
            float a[4], b[4];
#pragma unroll
            for (int i = 0; i < 4; i++) a[i] = As[kk][ty * 4 + i];
#pragma unroll
            for (int j = 0; j < 4; j++) b[j] = Bs[kk][tx * 4 + j];
#pragma unroll
            for (int i = 0; i < 4; i++)
#pragma unroll
                for (int j = 0; j < 4; j++) acc[i][j] = fmaf(a[i], b[j], acc[i][j]);
        }
        __syncthreads();
    }

#pragma unroll
    for (int i = 0; i < 4; i++) {
        int gm = bm + ty * 4 + i;
        if (gm >= M) continue;
#pragma unroll
        for (int j = 0; j < 4; j++) {
            int gn = bn + tx * 4 + j;
            if (gn >= N) continue;
            float v = acc[i][j];
            if (bias) v += bias[gn];
            if (addsrc) v += addsrc[(size_t)gm * N + gn];
            C[(size_t)gm * N + gn] = v;
        }
    }
}

// ---------------------------------------------------------------------------
// Causal depthwise conv (width 4) + SiLU. xz layout [t, 1024]; xin = first 512.
// ---------------------------------------------------------------------------
__global__ void conv_silu_kernel(const float* __restrict__ xz,
                                 const float* __restrict__ cw,
                                 float* __restrict__ u) {
    int idx = blockIdx.x * blockDim.x + threadIdx.x;
    if (idx >= TT * DI) return;
    int t = idx >> 9;   // /512
    int d = idx & 511;
    int l = t & 511;    // L = 512
    float acc = 0.f;
#pragma unroll
    for (int j = 0; j < 4; j++) {
        int ll = l - 3 + j;
        if (ll >= 0) acc = fmaf(cw[d * 4 + j], xz[(size_t)(t - 3 + j) * XZW + d], acc);
    }
    float s = 1.f / (1.f + __expf(-acc));
    u[idx] = acc * s;
}

// ---------------------------------------------------------------------------
// delta = softplus(dt @ dt_w^T + dt_b), dt = xdbc[:, :16]
// ---------------------------------------------------------------------------
__global__ void delta_kernel(const float* __restrict__ xdbc,
                             const float* __restrict__ dtw,
                             const float* __restrict__ dtb,
                             float* __restrict__ delta) {
    int idx = blockIdx.x * blockDim.x + threadIdx.x;
    if (idx >= TT * DI) return;
    int t = idx >> 9;
    int d = idx & 511;
    float s = dtb[d];
#pragma unroll
    for (int r = 0; r < DTR; r++) s = fmaf(xdbc[t * RXW + r], dtw[d * DTR + r], s);
    delta[idx] = (s > 20.f) ? s : log1pf(__expf(s));
}

// ---------------------------------------------------------------------------
// Selective scan. Thread = (b, d, n). 16-lane groups share d; y reduced over n.
// grid = B * (DI/16) = 128 blocks, 256 threads (16 d-groups x 16 n).
// ---------------------------------------------------------------------------
__global__ void scan_kernel(const float* __restrict__ delta,
                            const float* __restrict__ u,
                            const float* __restrict__ xdbc,
                            const float* __restrict__ A_log,
                            float* __restrict__ y) {
    int b = blockIdx.x >> 5;             // /32
    int dbase = (blockIdx.x & 31) << 4;  // *16
    int n = threadIdx.x & 15;
    int dg = threadIdx.x >> 4;
    int d = dbase + dg;
    float Ac = -__expf(A_log[d * DS + n]);
    float h = 0.f;
    int tbase = b << 9;
    for (int l = 0; l < LL; l++) {
        int t = tbase + l;
        float del = delta[(size_t)t * DI + d];     // same addr across 16 lanes (HW bcast)
        float uu = u[(size_t)t * DI + d];
        float Bn = xdbc[t * RXW + DTR + n];
        float Cn = xdbc[t * RXW + DTR + DS + n];
        h = fmaf(__expf(del * Ac), h, del * uu * Bn);
        float yp = h * Cn;
#pragma unroll
        for (int o = 8; o > 0; o >>= 1) yp += __shfl_xor_sync(0xffffffffu, yp, o, 16);
        if (n == 0) y[(size_t)t * DI + d] = yp;
    }
}

// ---------------------------------------------------------------------------
// Gate: yg = (y + u*D) * silu(z), z = xz[:, 512:]
// ---------------------------------------------------------------------------
__global__ void gate_kernel(const float* __restrict__ y,
                            const float* __restrict__ u,
                            const float* __restrict__ xz,
                            const float* __restrict__ Dp,
                            float* __restrict__ yg) {
    int idx = blockIdx.x * blockDim.x + threadIdx.x;
    if (idx >= TT * DI) return;
    int t = idx >> 9;
    int d = idx & 511;
    float z = xz[(size_t)t * XZW + DI + d];
    float sz = z / (1.f + __expf(-z));
    yg[idx] = (y[idx] + u[idx] * Dp[d]) * sz;
}

// ---------------------------------------------------------------------------
// Host launcher
// ---------------------------------------------------------------------------
extern "C" void kernel_launch(void* const* d_in, const int* in_sizes, int n_in,
                              void* d_out, int out_size) {
    const float* x      = (const float*)d_in[0];
    const float* norm_w = (const float*)d_in[1];
    const float* W_in   = (const float*)d_in[2];
    const float* b_in   = (const float*)d_in[3];
    const float* conv_w = (const float*)d_in[4];
    const float* W_x    = (const float*)d_in[5];
    const float* dt_w   = (const float*)d_in[6];
    const float* dt_b   = (const float*)d_in[7];
    const float* A_log  = (const float*)d_in[8];
    const float* Dp     = (const float*)d_in[9];
    const float* W_out  = (const float*)d_in[10];
    const float* b_out  = (const float*)d_in[11];
    float* xcur = (float*)d_out;

    float *xn, *xz, *u, *xdbc, *delta, *y, *yg;
    cudaGetSymbolAddress((void**)&xn, g_xn);
    cudaGetSymbolAddress((void**)&xz, g_xz);
    cudaGetSymbolAddress((void**)&u, g_u);
    cudaGetSymbolAddress((void**)&xdbc, g_xdbc);
    cudaGetSymbolAddress((void**)&delta, g_delta);
    cudaGetSymbolAddress((void**)&y, g_y);
    cudaGetSymbolAddress((void**)&yg, g_yg);

    cudaMemcpyAsync(xcur, x, (size_t)TT * DM * sizeof(float),
                    cudaMemcpyDeviceToDevice);

    const int ew_blocks = (TT * DI) / 256;  // 4096

    for (int i = 0; i < NL; i++) {
        rmsnorm_kernel<<<TT, 256>>>(xcur, norm_w + (size_t)i * DM, xn);

        gemm_tn_kernel<<<dim3(XZW / 64, TT / 64), 256>>>(
            xn, W_in + (size_t)i * XZW * DM, b_in + (size_t)i * XZW, nullptr,
            xz, TT, XZW, DM);

        conv_silu_kernel<<<ew_blocks, 256>>>(xz, conv_w + (size_t)i * DI * DC, u);

        gemm_tn_kernel<<<dim3(1, TT / 64), 256>>>(
            u, W_x + (size_t)i * RXW * DI, nullptr, nullptr,
            xdbc, TT, RXW, DI);

        delta_kernel<<<ew_blocks, 256>>>(xdbc, dt_w + (size_t)i * DI * DTR,
                                         dt_b + (size_t)i * DI, delta);

        scan_kernel<<<BB * (DI / 16), 256>>>(delta, u, xdbc,
                                             A_log + (size_t)i * DI * DS, y);

        gate_kernel<<<ew_blocks, 256>>>(y, u, xz, Dp + (size_t)i * DI, yg);

        gemm_tn_kernel<<<dim3(DM / 64, TT / 64), 256>>>(
            yg, W_out + (size_t)i * DM * DI, b_out + (size_t)i * DM, xcur,
            xcur, TT, DM, DI);
    }
}